// round 3
// baseline (speedup 1.0000x reference)
#include <cuda_runtime.h>

#define B_SZ 8192
#define T_SZ 32

// Scratch (static device globals; no runtime allocation)
__device__ float d_To[9];                 // readout tensor
__device__ float d_S[T_SZ * 18 * B_SZ];   // [t][k][b]

__device__ __forceinline__ float2 cmul(float2 a, float2 b) {
    return make_float2(a.x * b.x - a.y * b.y, a.x * b.y + a.y * b.x);
}

__device__ __forceinline__ unsigned long long fma2(unsigned long long a,
                                                   unsigned long long b,
                                                   unsigned long long c) {
    unsigned long long d;
    asm("fma.rn.f32x2 %0, %1, %2, %3;" : "=l"(d) : "l"(a), "l"(b), "l"(c));
    return d;
}
__device__ __forceinline__ unsigned long long pk2(float x) {
    unsigned long long r;
    asm("mov.b64 %0, {%1, %1};" : "=l"(r) : "f"(x));
    return r;
}

// ---------------------------------------------------------------------------
// Fused kernel A:
//   blocks 0..255 : per-block redundant precompute of the monomial tensor
//                   Ts[27][20] (smem), then S[t][k][b] for 4 elements/thread.
//   block 256     : computes readout tensor To -> d_To (9 threads), concurrent.
// ---------------------------------------------------------------------------
__global__ void __launch_bounds__(256) fused_phase1_kernel(
        const float* __restrict__ x_seq,
        const float* __restrict__ wrec,
        const float* __restrict__ wout) {
    const int tid = threadIdx.x;

    // ---------------- spare block: readout tensor To ----------------
    if (blockIdx.x == 256) {
        if (tid < 9) {
            int m = tid;
            float2 V[4][4];  // [col][row]
#pragma unroll
            for (int c2 = 0; c2 < 4; c2++)
#pragma unroll
                for (int r2 = 0; r2 < 4; r2++)
                    V[c2][r2] = make_float2(c2 == r2 ? 1.f : 0.f, 0.f);
#pragma unroll
            for (int l = 0; l < 2; l++) {
#pragma unroll
                for (int w = 0; w < 2; w++) {
                    float phi = wout[(l * 2 + w) * 3 + 0];
                    float th  = wout[(l * 2 + w) * 3 + 1];
                    float om  = wout[(l * 2 + w) * 3 + 2];
                    float s, c, sa, ca, sb, cb;
                    __sincosf(0.5f * th, &s, &c);
                    __sincosf(0.5f * (phi + om), &sa, &ca);
                    __sincosf(0.5f * (phi - om), &sb, &cb);
                    float2 r00 = make_float2( c * ca, -c * sa);
                    float2 r01 = make_float2(-s * cb, -s * sb);
                    float2 r10 = make_float2( s * cb, -s * sb);
                    float2 r11 = make_float2( c * ca,  c * sa);
                    int mask = 1 << (1 - w);
#pragma unroll
                    for (int col = 0; col < 4; col++) {
#pragma unroll
                        for (int i0 = 0; i0 < 4; i0++) {
                            if (i0 & mask) continue;
                            int i1 = i0 | mask;
                            float2 a0 = V[col][i0], a1 = V[col][i1];
                            float2 n0 = cmul(r00, a0), u01 = cmul(r01, a1);
                            n0.x += u01.x; n0.y += u01.y;
                            float2 n1 = cmul(r10, a0), u11 = cmul(r11, a1);
                            n1.x += u11.x; n1.y += u11.y;
                            V[col][i0] = n0;
                            V[col][i1] = n1;
                        }
                    }
                }
                // CNOT(0,1) then CNOT(1,0)
#pragma unroll
                for (int w = 0; w < 2; w++) {
                    int cm = 1 << (1 - w), tm = 1 << (1 - ((w + 1) & 1));
#pragma unroll
                    for (int col = 0; col < 4; col++)
#pragma unroll
                        for (int row = 0; row < 4; row++)
                            if ((row & cm) && !(row & tm)) {
                                float2 a = V[col][row], b2 = V[col][row | tm];
                                V[col][row] = b2;
                                V[col][row | tm] = a;
                            }
                }
            }
            float Mo[4][4];
#pragma unroll
            for (int s = 0; s < 4; s++)
#pragma unroll
                for (int t = 0; t < 4; t++) {
                    float acc = 0.f;
#pragma unroll
                    for (int k = 0; k < 4; k++) {
                        float2 vs = V[s][k], vt = V[t][k];
                        float re = vs.x * vt.x + vs.y * vt.y;
                        acc += ((k >> 1) & 1) ? -re : re;
                    }
                    Mo[s][t] = acc;
                }
            int d0 = m / 3, d1 = m % 3;
            int emask = (d0 == 1 ? 2 : 0) | (d1 == 1 ? 1 : 0);
            int xmask = (d0 == 2 ? 2 : 0) | (d1 == 2 ? 1 : 0);
            float sum = 0.f;
#pragma unroll
            for (int u = 0; u < 4; u++) {
                float sgn = (__popc(u & emask) & 1) ? -1.f : 1.f;
                sum += sgn * Mo[u][u ^ xmask];
            }
            d_To[m] = sum * 0.25f;
        }
        return;
    }

    // ---------------- per-block precompute of Ts ----------------
    __shared__ float2 G[10][4];        // rot gates
    __shared__ float2 Us[32][33];      // [col][row], padded vs bank conflicts
    __shared__ float  Ms[2][32][32];   // M_j = Re(U^H D_j U)
    __shared__ __align__(16) float Ts[27 * 20];

    if (tid < 10) {
        float phi = wrec[tid * 3 + 0];
        float th  = wrec[tid * 3 + 1];
        float om  = wrec[tid * 3 + 2];
        float s, c, sa, ca, sb, cb;
        __sincosf(0.5f * th, &s, &c);
        __sincosf(0.5f * (phi + om), &sa, &ca);
        __sincosf(0.5f * (phi - om), &sb, &cb);
        G[tid][0] = make_float2( c * ca, -c * sa);
        G[tid][1] = make_float2(-s * cb, -s * sb);
        G[tid][2] = make_float2( s * cb, -s * sb);
        G[tid][3] = make_float2( c * ca,  c * sa);
    }
    // U = I  (1024 entries, 4 per thread)
#pragma unroll
    for (int r = 0; r < 4; r++) {
        int idx = tid + r * 256;
        int col = idx >> 5, row = idx & 31;
        Us[col][row] = make_float2(col == row ? 1.f : 0.f, 0.f);
    }
    __syncthreads();

#pragma unroll
    for (int l = 0; l < 2; l++) {
        // Rot gates on wires 0..4  (512 pair-ops, 2 per thread)
#pragma unroll
        for (int w = 0; w < 5; w++) {
            float2 r00 = G[l * 5 + w][0], r01 = G[l * 5 + w][1];
            float2 r10 = G[l * 5 + w][2], r11 = G[l * 5 + w][3];
            int mask = 1 << (4 - w);
            int low = mask - 1;
#pragma unroll
            for (int r = 0; r < 2; r++) {
                int idx = tid + r * 256;
                int col = idx >> 4, p = idx & 15;
                int i0 = ((p & ~low) << 1) | (p & low);
                int i1 = i0 | mask;
                float2 a0 = Us[col][i0], a1 = Us[col][i1];
                float2 n0 = cmul(r00, a0), u01 = cmul(r01, a1);
                n0.x += u01.x; n0.y += u01.y;
                float2 n1 = cmul(r10, a0), u11 = cmul(r11, a1);
                n1.x += u11.x; n1.y += u11.y;
                Us[col][i0] = n0;
                Us[col][i1] = n1;
            }
            __syncthreads();
        }
        // CNOT ring (range r = l+1) fused into one permutation
        {
            float2 v[4];
            int dcol[4], drow[4];
#pragma unroll
            for (int r = 0; r < 4; r++) {
                int idx = tid + r * 256;
                int col = idx >> 5, row = idx & 31;
                int rr = l + 1;
                int j = row;
#pragma unroll
                for (int w = 4; w >= 0; w--) {
                    int cm = 1 << (4 - w);
                    int tm = 1 << (4 - ((w + rr) % 5));
                    if (j & cm) j ^= tm;
                }
                v[r] = Us[col][j];
                dcol[r] = col; drow[r] = row;
            }
            __syncthreads();
#pragma unroll
            for (int r = 0; r < 4; r++) Us[dcol[r]][drow[r]] = v[r];
            __syncthreads();
        }
    }

    // M_j[s][t] = Re( sum_k conj(U[k][s]) d_j(k) U[k][t] ), 4 entries/thread
#pragma unroll
    for (int r = 0; r < 4; r++) {
        int idx = tid + r * 256;
        int s = idx >> 5, t = idx & 31;
        float m0 = 0.f, m1 = 0.f;
#pragma unroll
        for (int k = 0; k < 32; k++) {
            float2 us = Us[s][k], ut = Us[t][k];
            float re = us.x * ut.x + us.y * ut.y;
            m0 += ((k >> 1) & 1) ? -re : re;
            m1 += (k & 1) ? -re : re;
        }
        Ms[0][s][t] = m0;
        Ms[1][s][t] = m1;
    }
    __syncthreads();

    // T_j[m] -> Ts smem  (486 entries, 2 per thread) + zero pad
#pragma unroll
    for (int r = 0; r < 2; r++) {
        int idx = tid + r * 256;
        if (idx < 486) {
            int j = idx / 243, m = idx % 243;
            int dg[5];
            int mm = m;
#pragma unroll
            for (int w = 4; w >= 0; w--) { dg[w] = mm % 3; mm /= 3; }
            int emask = 0, xmask = 0;
#pragma unroll
            for (int w = 0; w < 5; w++) {
                if (dg[w] == 1) emask |= 1 << (4 - w);
                if (dg[w] == 2) xmask |= 1 << (4 - w);
            }
            float sum = 0.f;
#pragma unroll
            for (int u = 0; u < 32; u++) {
                float sgn = (__popc(u & emask) & 1) ? -1.f : 1.f;
                sum += sgn * Ms[j][u][u ^ xmask];
            }
            Ts[(m / 9) * 20 + (m % 9) * 2 + j] = sum * (1.f / 32.f);
        }
    }
    if (tid < 27) {
        Ts[tid * 20 + 18] = 0.f;
        Ts[tid * 20 + 19] = 0.f;
    }
    __syncthreads();

    // ---------------- S computation: 4 elements per thread ----------------
    unsigned tbase = (unsigned)__cvta_generic_to_shared(Ts);
#pragma unroll
    for (int i = 0; i < 4; i++) {
        int e = blockIdx.x * 1024 + i * 256 + tid;
        int b = e & (B_SZ - 1);
        int t = e >> 13;
        const float* xp = x_seq + ((size_t)t * B_SZ + b) * 3;
        float x0 = xp[0], x1 = xp[1], x2 = xp[2];
        float s0, c0, s1, c1, s2, c2;
        __sincosf(x0, &s0, &c0);
        __sincosf(x1, &s1, &c1);
        __sincosf(x2, &s2, &c2);
        float g0[3] = {1.f, c0, s0};
        float g1[3] = {1.f, c1, s1};
        float g2[3] = {1.f, c2, s2};

        unsigned long long acc[10];
#pragma unroll
        for (int q = 0; q < 10; q++) acc[q] = 0ull;

#pragma unroll
        for (int m0 = 0; m0 < 3; m0++) {
#pragma unroll
            for (int m1 = 0; m1 < 3; m1++) {
                float p01 = g0[m0] * g1[m1];
#pragma unroll
                for (int m2 = 0; m2 < 3; m2++) {
                    float p = p01 * g2[m2];
                    unsigned long long p2 = pk2(p);
                    int mx = (m0 * 3 + m1) * 3 + m2;
                    unsigned ra = tbase + mx * 80;
#pragma unroll
                    for (int q = 0; q < 5; q++) {
                        unsigned long long t0, t1;
                        asm volatile("ld.shared.v2.b64 {%0,%1}, [%2];"
                                     : "=l"(t0), "=l"(t1) : "r"(ra + q * 16));
                        acc[2 * q]     = fma2(p2, t0, acc[2 * q]);
                        acc[2 * q + 1] = fma2(p2, t1, acc[2 * q + 1]);
                    }
                }
            }
        }

        size_t base = (size_t)t * 18 * B_SZ + b;
#pragma unroll
        for (int mh = 0; mh < 9; mh++) {
            float lo, hi;
            asm("mov.b64 {%0,%1}, %2;" : "=f"(lo), "=f"(hi) : "l"(acc[mh]));
            d_S[base + (size_t)(2 * mh) * B_SZ]     = lo;
            d_S[base + (size_t)(2 * mh + 1) * B_SZ] = hi;
        }
    }
}

// ---------------------------------------------------------------------------
// Phase 2: sequential recurrence over T steps + fused readout.
// ---------------------------------------------------------------------------
__global__ void __launch_bounds__(128) phase2_kernel(float* __restrict__ out) {
    int b = blockIdx.x * 128 + threadIdx.x;
    float To[9];
#pragma unroll
    for (int i = 0; i < 9; i++) To[i] = d_To[i];

    float h0 = 0.f, h1 = 0.f;
    float Sc[18];
    const float* Sb = d_S + b;
#pragma unroll
    for (int k = 0; k < 18; k++) Sc[k] = Sb[(size_t)k * B_SZ];

#pragma unroll
    for (int t = 0; t < T_SZ; t++) {
        float Sn[18];
        if (t < T_SZ - 1) {
            const float* p = Sb + (size_t)(t + 1) * 18 * B_SZ;
#pragma unroll
            for (int k = 0; k < 18; k++) Sn[k] = p[(size_t)k * B_SZ];
        }
        float sh0, ch0, sh1, ch1;
        __sincosf(h0, &sh0, &ch0);
        __sincosf(h1, &sh1, &ch1);
        float Q[9];
        Q[0] = 1.f;        Q[1] = ch1;        Q[2] = sh1;
        Q[3] = ch0;        Q[4] = ch0 * ch1;  Q[5] = ch0 * sh1;
        Q[6] = sh0;        Q[7] = sh0 * ch1;  Q[8] = sh0 * sh1;
        float a0 = 0.f, a1 = 0.f;
#pragma unroll
        for (int mh = 0; mh < 9; mh++) {
            a0 += Sc[2 * mh] * Q[mh];
            a1 += Sc[2 * mh + 1] * Q[mh];
        }
        h0 = a0;
        h1 = a1;
        if (t < T_SZ - 1) {
#pragma unroll
            for (int k = 0; k < 18; k++) Sc[k] = Sn[k];
        }
    }

    // Readout
    float sh0, ch0, sh1, ch1;
    __sincosf(h0, &sh0, &ch0);
    __sincosf(h1, &sh1, &ch1);
    float Q[9] = {1.f, ch1, sh1, ch0, ch0 * ch1, ch0 * sh1, sh0, sh0 * ch1, sh0 * sh1};
    float r = 0.f;
#pragma unroll
    for (int m = 0; m < 9; m++) r += To[m] * Q[m];
    out[b] = r;
}

// ---------------------------------------------------------------------------
extern "C" void kernel_launch(void* const* d_in, const int* in_sizes, int n_in,
                              void* d_out, int out_size) {
    const float* x_seq = nullptr;
    const float* w_rec = nullptr;
    const float* w_out = nullptr;
    for (int i = 0; i < n_in; i++) {
        if (in_sizes[i] == T_SZ * B_SZ * 3) x_seq = (const float*)d_in[i];
        else if (in_sizes[i] == 30)         w_rec = (const float*)d_in[i];
        else if (in_sizes[i] == 12)         w_out = (const float*)d_in[i];
    }
    float* out = (float*)d_out;

    fused_phase1_kernel<<<257, 256>>>(x_seq, w_rec, w_out);
    phase2_kernel<<<B_SZ / 128, 128>>>(out);
}

// round 4
// speedup vs baseline: 1.7029x; 1.7029x over previous
#include <cuda_runtime.h>

#define B_SZ 8192
#define T_SZ 32

// Scratch (static device globals; no runtime allocation)
__device__ float d_Tp[27 * 20];                 // [mx][k], k = mh*2+j, pads zero
__device__ float d_To[9];                       // readout tensor
__device__ float d_S[T_SZ * B_SZ * 20];         // [t][b][20]  (18 used + 2 pad)

__device__ __forceinline__ float2 cmul(float2 a, float2 b) {
    return make_float2(a.x * b.x - a.y * b.y, a.x * b.y + a.y * b.x);
}

__device__ __forceinline__ unsigned long long fma2(unsigned long long a,
                                                   unsigned long long b,
                                                   unsigned long long c) {
    unsigned long long d;
    asm("fma.rn.f32x2 %0, %1, %2, %3;" : "=l"(d) : "l"(a), "l"(b), "l"(c));
    return d;
}
__device__ __forceinline__ unsigned long long pk2(float x) {
    unsigned long long r;
    asm("mov.b64 %0, {%1, %1};" : "=l"(r) : "f"(x));
    return r;
}

// ---------------------------------------------------------------------------
// Precompute (1 block, 1024 threads): entangler U -> monomial tensor d_Tp,
// plus readout tensor d_To (computed concurrently by a spare warp).
// U stored as Us[row][col] (padded) so all smem stages are conflict-free.
// ---------------------------------------------------------------------------
__global__ void __launch_bounds__(1024) precompute_kernel(const float* __restrict__ wrec,
                                                          const float* __restrict__ wout) {
    __shared__ float2 G[10][4];        // rot gates
    __shared__ float2 Us[32][33];      // [row][col], padded
    __shared__ float  Ms[2][32][33];   // M_j[s][t], padded
    const int tid = threadIdx.x;

    if (tid < 10) {
        float phi = wrec[tid * 3 + 0];
        float th  = wrec[tid * 3 + 1];
        float om  = wrec[tid * 3 + 2];
        float s, c, sa, ca, sb, cb;
        __sincosf(0.5f * th, &s, &c);
        __sincosf(0.5f * (phi + om), &sa, &ca);
        __sincosf(0.5f * (phi - om), &sb, &cb);
        G[tid][0] = make_float2( c * ca, -c * sa);
        G[tid][1] = make_float2(-s * cb, -s * sb);
        G[tid][2] = make_float2( s * cb, -s * sb);
        G[tid][3] = make_float2( c * ca,  c * sa);
    }
    // U = I
    {
        int row = tid >> 5, col = tid & 31;
        Us[row][col] = make_float2(row == col ? 1.f : 0.f, 0.f);
    }
    __syncthreads();

#pragma unroll
    for (int l = 0; l < 2; l++) {
        // Rot gates on wires 0..4. 512 threads: col = lane-ish (conflict-free)
#pragma unroll
        for (int w = 0; w < 5; w++) {
            if (tid < 512) {
                int col = tid & 31, p = tid >> 5;   // p = 0..15
                int mask = 1 << (4 - w);
                int low = mask - 1;
                int i0 = ((p & ~low) << 1) | (p & low);
                int i1 = i0 | mask;
                float2 r00 = G[l * 5 + w][0], r01 = G[l * 5 + w][1];
                float2 r10 = G[l * 5 + w][2], r11 = G[l * 5 + w][3];
                float2 a0 = Us[i0][col], a1 = Us[i1][col];
                float2 n0 = cmul(r00, a0), u01 = cmul(r01, a1);
                n0.x += u01.x; n0.y += u01.y;
                float2 n1 = cmul(r10, a0), u11 = cmul(r11, a1);
                n1.x += u11.x; n1.y += u11.y;
                Us[i0][col] = n0;
                Us[i1][col] = n1;
            }
            __syncthreads();
        }
        // CNOT ring (range r = l+1) fused into one permutation on rows
        {
            int row = tid >> 5, col = tid & 31;
            int rr = l + 1;
            int j = row;
#pragma unroll
            for (int w = 4; w >= 0; w--) {
                int cm = 1 << (4 - w);
                int tm = 1 << (4 - ((w + rr) % 5));
                if (j & cm) j ^= tm;
            }
            float2 v = Us[j][col];
            __syncthreads();
            Us[row][col] = v;
            __syncthreads();
        }
    }

    // M_j[s][t] = sum_k Us[k][s].Us[k][t] with diag sign; lanes index t.
    {
        int s = tid >> 5, t = tid & 31;
        float m0 = 0.f, m1 = 0.f;
#pragma unroll
        for (int k = 0; k < 32; k++) {
            float2 us = Us[k][s], ut = Us[k][t];
            float re = us.x * ut.x + us.y * ut.y;
            m0 += ((k >> 1) & 1) ? -re : re;
            m1 += (k & 1) ? -re : re;
        }
        Ms[0][s][t] = m0;
        Ms[1][s][t] = m1;
    }
    __syncthreads();

    // T_j[m] = (1/32) sum_u sgn(u) * M_j[u][u^xmask]  -> d_Tp
    if (tid < 486) {
        int j = tid / 243, m = tid % 243;
        int dg[5];
        int mm = m;
#pragma unroll
        for (int w = 4; w >= 0; w--) { dg[w] = mm % 3; mm /= 3; }
        int emask = 0, xmask = 0;
#pragma unroll
        for (int w = 0; w < 5; w++) {
            if (dg[w] == 1) emask |= 1 << (4 - w);
            if (dg[w] == 2) xmask |= 1 << (4 - w);
        }
        float sum = 0.f;
#pragma unroll
        for (int u = 0; u < 32; u++) {
            float sgn = (__popc(u & emask) & 1) ? -1.f : 1.f;
            sum += sgn * Ms[j][u][u ^ xmask];
        }
        d_Tp[(m / 9) * 20 + (m % 9) * 2 + j] = sum * (1.f / 32.f);
    }
    // zero pad k = 18,19
    if (tid >= 640 && tid < 640 + 54) {
        int i = tid - 640;
        d_Tp[(i >> 1) * 20 + 18 + (i & 1)] = 0.f;
    }

    // Readout tensor To (9 threads in warp 16, concurrent with T-stage)
    if (tid >= 512 && tid < 521) {
        int m = tid - 512;
        float2 V[4][4];
#pragma unroll
        for (int c2 = 0; c2 < 4; c2++)
#pragma unroll
            for (int r2 = 0; r2 < 4; r2++)
                V[c2][r2] = make_float2(c2 == r2 ? 1.f : 0.f, 0.f);
#pragma unroll
        for (int l = 0; l < 2; l++) {
#pragma unroll
            for (int w = 0; w < 2; w++) {
                float phi = wout[(l * 2 + w) * 3 + 0];
                float th  = wout[(l * 2 + w) * 3 + 1];
                float om  = wout[(l * 2 + w) * 3 + 2];
                float s, c, sa, ca, sb, cb;
                __sincosf(0.5f * th, &s, &c);
                __sincosf(0.5f * (phi + om), &sa, &ca);
                __sincosf(0.5f * (phi - om), &sb, &cb);
                float2 r00 = make_float2( c * ca, -c * sa);
                float2 r01 = make_float2(-s * cb, -s * sb);
                float2 r10 = make_float2( s * cb, -s * sb);
                float2 r11 = make_float2( c * ca,  c * sa);
                int mask = 1 << (1 - w);
#pragma unroll
                for (int col = 0; col < 4; col++) {
#pragma unroll
                    for (int i0 = 0; i0 < 4; i0++) {
                        if (i0 & mask) continue;
                        int i1 = i0 | mask;
                        float2 a0 = V[col][i0], a1 = V[col][i1];
                        float2 n0 = cmul(r00, a0), u01 = cmul(r01, a1);
                        n0.x += u01.x; n0.y += u01.y;
                        float2 n1 = cmul(r10, a0), u11 = cmul(r11, a1);
                        n1.x += u11.x; n1.y += u11.y;
                        V[col][i0] = n0;
                        V[col][i1] = n1;
                    }
                }
            }
#pragma unroll
            for (int w = 0; w < 2; w++) {
                int cm = 1 << (1 - w), tm = 1 << (1 - ((w + 1) & 1));
#pragma unroll
                for (int col = 0; col < 4; col++)
#pragma unroll
                    for (int row = 0; row < 4; row++)
                        if ((row & cm) && !(row & tm)) {
                            float2 a = V[col][row], b2 = V[col][row | tm];
                            V[col][row] = b2;
                            V[col][row | tm] = a;
                        }
            }
        }
        float Mo[4][4];
#pragma unroll
        for (int s = 0; s < 4; s++)
#pragma unroll
            for (int t = 0; t < 4; t++) {
                float acc = 0.f;
#pragma unroll
                for (int k = 0; k < 4; k++) {
                    float2 vs = V[s][k], vt = V[t][k];
                    float re = vs.x * vt.x + vs.y * vt.y;
                    acc += ((k >> 1) & 1) ? -re : re;
                }
                Mo[s][t] = acc;
            }
        int d0 = m / 3, d1 = m % 3;
        int emask = (d0 == 1 ? 2 : 0) | (d1 == 1 ? 1 : 0);
        int xmask = (d0 == 2 ? 2 : 0) | (d1 == 2 ? 1 : 0);
        float sum = 0.f;
#pragma unroll
        for (int u = 0; u < 4; u++) {
            float sgn = (__popc(u & emask) & 1) ? -1.f : 1.f;
            sum += sgn * Mo[u][u ^ xmask];
        }
        d_To[m] = sum * 0.25f;
    }
}

// ---------------------------------------------------------------------------
// Phase 1: S[t][b][0..19] = P(x[t,b]) . T   (f32x2-packed FMAs, T in smem)
// ---------------------------------------------------------------------------
__global__ void __launch_bounds__(256) phase1_kernel(const float* __restrict__ x_seq) {
    __shared__ __align__(16) float Ts[27 * 20];
    const int tid = threadIdx.x;
    for (int i = tid; i < 540; i += 256) Ts[i] = d_Tp[i];
    __syncthreads();

    int e = blockIdx.x * 256 + tid;
    int b = e & (B_SZ - 1);
    int t = e >> 13;
    const float* xp = x_seq + ((size_t)t * B_SZ + b) * 3;
    float x0 = xp[0], x1 = xp[1], x2 = xp[2];
    float s0, c0, s1, c1, s2, c2;
    __sincosf(x0, &s0, &c0);
    __sincosf(x1, &s1, &c1);
    __sincosf(x2, &s2, &c2);
    float g0[3] = {1.f, c0, s0};
    float g1[3] = {1.f, c1, s1};
    float g2[3] = {1.f, c2, s2};

    unsigned long long acc[10];
#pragma unroll
    for (int q = 0; q < 10; q++) acc[q] = 0ull;

    unsigned tbase = (unsigned)__cvta_generic_to_shared(Ts);
#pragma unroll
    for (int m0 = 0; m0 < 3; m0++) {
#pragma unroll
        for (int m1 = 0; m1 < 3; m1++) {
            float p01 = g0[m0] * g1[m1];
#pragma unroll
            for (int m2 = 0; m2 < 3; m2++) {
                float p = p01 * g2[m2];
                unsigned long long p2 = pk2(p);
                int mx = (m0 * 3 + m1) * 3 + m2;
                unsigned ra = tbase + mx * 80;
#pragma unroll
                for (int q = 0; q < 5; q++) {
                    unsigned long long t0, t1;
                    asm volatile("ld.shared.v2.b64 {%0,%1}, [%2];"
                                 : "=l"(t0), "=l"(t1) : "r"(ra + q * 16));
                    acc[2 * q]     = fma2(p2, t0, acc[2 * q]);
                    acc[2 * q + 1] = fma2(p2, t1, acc[2 * q + 1]);
                }
            }
        }
    }

    // Store 20 floats (18 data + 2 zero pads) as 5 float4s, 16B-aligned.
    float4* dst = reinterpret_cast<float4*>(d_S + ((size_t)t * B_SZ + b) * 20);
#pragma unroll
    for (int q = 0; q < 5; q++) {
        float l0, h0v, l1, h1v;
        asm("mov.b64 {%0,%1}, %2;" : "=f"(l0), "=f"(h0v) : "l"(acc[2 * q]));
        asm("mov.b64 {%0,%1}, %2;" : "=f"(l1), "=f"(h1v) : "l"(acc[2 * q + 1]));
        dst[q] = make_float4(l0, h0v, l1, h1v);
    }
}

// ---------------------------------------------------------------------------
// Phase 2: sequential recurrence, 4-step-deep float4 register prefetch.
// ---------------------------------------------------------------------------
__global__ void __launch_bounds__(64) phase2_kernel(float* __restrict__ out) {
    int b = blockIdx.x * 64 + threadIdx.x;
    const float4* __restrict__ Sb =
        reinterpret_cast<const float4*>(d_S + (size_t)b * 20);
    const size_t tstride = (size_t)B_SZ * 5;   // in float4 units

    float4 buf[4][5];
#pragma unroll
    for (int d = 0; d < 4; d++) {
        const float4* p = Sb + (size_t)d * tstride;
#pragma unroll
        for (int q = 0; q < 5; q++) buf[d][q] = __ldg(p + q);
    }

    float h0 = 0.f, h1 = 0.f;
#pragma unroll
    for (int t = 0; t < T_SZ; t++) {
        float Sc[20];
#pragma unroll
        for (int q = 0; q < 5; q++) {
            Sc[4 * q + 0] = buf[t & 3][q].x;
            Sc[4 * q + 1] = buf[t & 3][q].y;
            Sc[4 * q + 2] = buf[t & 3][q].z;
            Sc[4 * q + 3] = buf[t & 3][q].w;
        }
        // prefetch step t+4 into the slot just freed
        if (t + 4 < T_SZ) {
            const float4* p = Sb + (size_t)(t + 4) * tstride;
#pragma unroll
            for (int q = 0; q < 5; q++) buf[t & 3][q] = __ldg(p + q);
        }
        float sh0, ch0, sh1, ch1;
        __sincosf(h0, &sh0, &ch0);
        __sincosf(h1, &sh1, &ch1);
        float Q[9];
        Q[0] = 1.f;        Q[1] = ch1;        Q[2] = sh1;
        Q[3] = ch0;        Q[4] = ch0 * ch1;  Q[5] = ch0 * sh1;
        Q[6] = sh0;        Q[7] = sh0 * ch1;  Q[8] = sh0 * sh1;
        float a0 = 0.f, a1 = 0.f;
#pragma unroll
        for (int mh = 0; mh < 9; mh++) {
            a0 += Sc[2 * mh] * Q[mh];
            a1 += Sc[2 * mh + 1] * Q[mh];
        }
        h0 = a0;
        h1 = a1;
    }

    // Readout
    float To[9];
#pragma unroll
    for (int i = 0; i < 9; i++) To[i] = d_To[i];
    float sh0, ch0, sh1, ch1;
    __sincosf(h0, &sh0, &ch0);
    __sincosf(h1, &sh1, &ch1);
    float Q[9] = {1.f, ch1, sh1, ch0, ch0 * ch1, ch0 * sh1, sh0, sh0 * ch1, sh0 * sh1};
    float r = 0.f;
#pragma unroll
    for (int m = 0; m < 9; m++) r += To[m] * Q[m];
    out[b] = r;
}

// ---------------------------------------------------------------------------
extern "C" void kernel_launch(void* const* d_in, const int* in_sizes, int n_in,
                              void* d_out, int out_size) {
    const float* x_seq = nullptr;
    const float* w_rec = nullptr;
    const float* w_out = nullptr;
    for (int i = 0; i < n_in; i++) {
        if (in_sizes[i] == T_SZ * B_SZ * 3) x_seq = (const float*)d_in[i];
        else if (in_sizes[i] == 30)         w_rec = (const float*)d_in[i];
        else if (in_sizes[i] == 12)         w_out = (const float*)d_in[i];
    }
    float* out = (float*)d_out;

    precompute_kernel<<<1, 1024>>>(w_rec, w_out);
    phase1_kernel<<<(T_SZ * B_SZ) / 256, 256>>>(x_seq);
    phase2_kernel<<<B_SZ / 64, 64>>>(out);
}

// round 5
// speedup vs baseline: 1.7686x; 1.0386x over previous
#include <cuda_runtime.h>

#define B_SZ 8192
#define T_SZ 32

// Static device scratch
__device__ float d_Tp[27 * 20];   // [mx][k], k = mh*2+j, k=18,19 zero pad
__device__ float d_To[9];         // readout tensor

__device__ __forceinline__ float2 cmul(float2 a, float2 b) {
    return make_float2(a.x * b.x - a.y * b.y, a.x * b.y + a.y * b.x);
}

__device__ __forceinline__ unsigned long long fma2(unsigned long long a,
                                                   unsigned long long b,
                                                   unsigned long long c) {
    unsigned long long d;
    asm("fma.rn.f32x2 %0, %1, %2, %3;" : "=l"(d) : "l"(a), "l"(b), "l"(c));
    return d;
}
__device__ __forceinline__ unsigned long long pk2(float x) {
    unsigned long long r;
    asm("mov.b64 %0, {%1, %1};" : "=l"(r) : "f"(x));
    return r;
}

// ---------------------------------------------------------------------------
// Precompute (1 block, 1024 threads). U stored as separate real/imag float
// planes -> stride-1 word addressing -> conflict-free smem in every stage.
// ---------------------------------------------------------------------------
__global__ void __launch_bounds__(1024) precompute_kernel(const float* __restrict__ wrec,
                                                          const float* __restrict__ wout) {
    __shared__ float2 G[10][4];
    __shared__ float UsR[32][33];
    __shared__ float UsI[32][33];
    __shared__ float Ms[2][32][33];
    const int tid = threadIdx.x;

    if (tid < 10) {
        float phi = wrec[tid * 3 + 0];
        float th  = wrec[tid * 3 + 1];
        float om  = wrec[tid * 3 + 2];
        float s, c, sa, ca, sb, cb;
        __sincosf(0.5f * th, &s, &c);
        __sincosf(0.5f * (phi + om), &sa, &ca);
        __sincosf(0.5f * (phi - om), &sb, &cb);
        G[tid][0] = make_float2( c * ca, -c * sa);
        G[tid][1] = make_float2(-s * cb, -s * sb);
        G[tid][2] = make_float2( s * cb, -s * sb);
        G[tid][3] = make_float2( c * ca,  c * sa);
    }
    {
        int row = tid >> 5, col = tid & 31;
        UsR[row][col] = (row == col) ? 1.f : 0.f;
        UsI[row][col] = 0.f;
    }
    __syncthreads();

#pragma unroll
    for (int l = 0; l < 2; l++) {
#pragma unroll
        for (int w = 0; w < 5; w++) {
            if (tid < 512) {
                int col = tid & 31, p = tid >> 5;   // p warp-uniform
                int mask = 1 << (4 - w);
                int low = mask - 1;
                int i0 = ((p & ~low) << 1) | (p & low);
                int i1 = i0 | mask;
                float2 r00 = G[l * 5 + w][0], r01 = G[l * 5 + w][1];
                float2 r10 = G[l * 5 + w][2], r11 = G[l * 5 + w][3];
                float2 a0 = make_float2(UsR[i0][col], UsI[i0][col]);
                float2 a1 = make_float2(UsR[i1][col], UsI[i1][col]);
                float2 n0 = cmul(r00, a0), u01 = cmul(r01, a1);
                n0.x += u01.x; n0.y += u01.y;
                float2 n1 = cmul(r10, a0), u11 = cmul(r11, a1);
                n1.x += u11.x; n1.y += u11.y;
                UsR[i0][col] = n0.x; UsI[i0][col] = n0.y;
                UsR[i1][col] = n1.x; UsI[i1][col] = n1.y;
            }
            __syncthreads();
        }
        // CNOT ring fused into one permutation on rows
        {
            int row = tid >> 5, col = tid & 31;
            int rr = l + 1;
            int j = row;
#pragma unroll
            for (int w = 4; w >= 0; w--) {
                int cm = 1 << (4 - w);
                int tm = 1 << (4 - ((w + rr) % 5));
                if (j & cm) j ^= tm;
            }
            float vr = UsR[j][col], vi = UsI[j][col];
            __syncthreads();
            UsR[row][col] = vr;
            UsI[row][col] = vi;
            __syncthreads();
        }
    }

    // M_j[s][t]: s warp-uniform (broadcast), t = lane (conflict-free)
    {
        int s = tid >> 5, t = tid & 31;
        float m0 = 0.f, m1 = 0.f;
#pragma unroll
        for (int k = 0; k < 32; k++) {
            float ar = UsR[k][s], ai = UsI[k][s];
            float br = UsR[k][t], bi = UsI[k][t];
            float re = ar * br + ai * bi;
            m0 += ((k >> 1) & 1) ? -re : re;
            m1 += (k & 1) ? -re : re;
        }
        Ms[0][s][t] = m0;
        Ms[1][s][t] = m1;
    }
    __syncthreads();

    // T tensor -> d_Tp
    if (tid < 486) {
        int j = tid / 243, m = tid % 243;
        int dg[5];
        int mm = m;
#pragma unroll
        for (int w = 4; w >= 0; w--) { dg[w] = mm % 3; mm /= 3; }
        int emask = 0, xmask = 0;
#pragma unroll
        for (int w = 0; w < 5; w++) {
            if (dg[w] == 1) emask |= 1 << (4 - w);
            if (dg[w] == 2) xmask |= 1 << (4 - w);
        }
        float sum = 0.f;
#pragma unroll
        for (int u = 0; u < 32; u++) {
            float sgn = (__popc(u & emask) & 1) ? -1.f : 1.f;
            sum += sgn * Ms[j][u][u ^ xmask];
        }
        d_Tp[(m / 9) * 20 + (m % 9) * 2 + j] = sum * (1.f / 32.f);
    }
    if (tid >= 640 && tid < 640 + 54) {
        int i = tid - 640;
        d_Tp[(i >> 1) * 20 + 18 + (i & 1)] = 0.f;
    }

    // Readout tensor To (warp 16, lanes 0..8)
    if (tid >= 512 && tid < 521) {
        int m = tid - 512;
        float2 V[4][4];
#pragma unroll
        for (int c2 = 0; c2 < 4; c2++)
#pragma unroll
            for (int r2 = 0; r2 < 4; r2++)
                V[c2][r2] = make_float2(c2 == r2 ? 1.f : 0.f, 0.f);
#pragma unroll
        for (int l = 0; l < 2; l++) {
#pragma unroll
            for (int w = 0; w < 2; w++) {
                float phi = wout[(l * 2 + w) * 3 + 0];
                float th  = wout[(l * 2 + w) * 3 + 1];
                float om  = wout[(l * 2 + w) * 3 + 2];
                float s, c, sa, ca, sb, cb;
                __sincosf(0.5f * th, &s, &c);
                __sincosf(0.5f * (phi + om), &sa, &ca);
                __sincosf(0.5f * (phi - om), &sb, &cb);
                float2 r00 = make_float2( c * ca, -c * sa);
                float2 r01 = make_float2(-s * cb, -s * sb);
                float2 r10 = make_float2( s * cb, -s * sb);
                float2 r11 = make_float2( c * ca,  c * sa);
                int mask = 1 << (1 - w);
#pragma unroll
                for (int col = 0; col < 4; col++) {
#pragma unroll
                    for (int i0 = 0; i0 < 4; i0++) {
                        if (i0 & mask) continue;
                        int i1 = i0 | mask;
                        float2 a0 = V[col][i0], a1 = V[col][i1];
                        float2 n0 = cmul(r00, a0), u01 = cmul(r01, a1);
                        n0.x += u01.x; n0.y += u01.y;
                        float2 n1 = cmul(r10, a0), u11 = cmul(r11, a1);
                        n1.x += u11.x; n1.y += u11.y;
                        V[col][i0] = n0;
                        V[col][i1] = n1;
                    }
                }
            }
#pragma unroll
            for (int w = 0; w < 2; w++) {
                int cm = 1 << (1 - w), tm = 1 << (1 - ((w + 1) & 1));
#pragma unroll
                for (int col = 0; col < 4; col++)
#pragma unroll
                    for (int row = 0; row < 4; row++)
                        if ((row & cm) && !(row & tm)) {
                            float2 a = V[col][row], b2 = V[col][row | tm];
                            V[col][row] = b2;
                            V[col][row | tm] = a;
                        }
            }
        }
        float Mo[4][4];
#pragma unroll
        for (int s = 0; s < 4; s++)
#pragma unroll
            for (int t = 0; t < 4; t++) {
                float acc = 0.f;
#pragma unroll
                for (int k = 0; k < 4; k++) {
                    float2 vs = V[s][k], vt = V[t][k];
                    float re = vs.x * vt.x + vs.y * vt.y;
                    acc += ((k >> 1) & 1) ? -re : re;
                }
                Mo[s][t] = acc;
            }
        int d0 = m / 3, d1 = m % 3;
        int emask = (d0 == 1 ? 2 : 0) | (d1 == 1 ? 1 : 0);
        int xmask = (d0 == 2 ? 2 : 0) | (d1 == 2 ? 1 : 0);
        float sum = 0.f;
#pragma unroll
        for (int u = 0; u < 4; u++) {
            float sgn = (__popc(u & emask) & 1) ? -1.f : 1.f;
            sum += sgn * Mo[u][u ^ xmask];
        }
        d_To[m] = sum * 0.25f;
    }
}

// ---------------------------------------------------------------------------
// Fused main kernel: 4 lanes per batch element (quad). Lane ql owns m2 digit
// ql (lane 3 multiplies by zero). Per step: compute partial S on the fly from
// x_t, dot with Q(h), quad-reduce via shfl. No intermediate global traffic.
// ---------------------------------------------------------------------------
__global__ void __launch_bounds__(256) main_kernel(const float* __restrict__ x_seq,
                                                   float* __restrict__ out) {
    __shared__ __align__(16) float Ts[27 * 20];
    const int tid = threadIdx.x;
    for (int i = tid; i < 540; i += 256) Ts[i] = d_Tp[i];
    __syncthreads();

    const int g = blockIdx.x * 256 + tid;
    const int b = g >> 2;
    const int ql = g & 3;

    unsigned tb = (unsigned)__cvta_generic_to_shared(Ts);
    if (ql == 1) tb += 80;
    else if (ql == 2) tb += 160;
    // ql==0 and ql==3 use base 0 (lane 3 contributes zero via g2v=0)

    const float* xp = x_seq + (size_t)b * 3;
    float xc0 = __ldg(xp + 0), xc1 = __ldg(xp + 1), xc2 = __ldg(xp + 2);

    float h0 = 0.f, h1 = 0.f;

#pragma unroll
    for (int t = 0; t < T_SZ; t++) {
        // prefetch next step's x
        float xn0 = 0.f, xn1 = 0.f, xn2 = 0.f;
        if (t < T_SZ - 1) {
            const float* p = xp + (size_t)(t + 1) * B_SZ * 3;
            xn0 = __ldg(p + 0); xn1 = __ldg(p + 1); xn2 = __ldg(p + 2);
        }

        float s0, c0, s1, c1, s2, c2;
        __sincosf(xc0, &s0, &c0);
        __sincosf(xc1, &s1, &c1);
        __sincosf(xc2, &s2, &c2);
        float g2v = (ql == 0) ? 1.f : (ql == 1) ? c2 : (ql == 2) ? s2 : 0.f;

        // P[m01] = g0[m0]*g1[m1]*g2[ql], m01 = m0*3+m1 (compile-time indices)
        float pa = g2v, pb = c1 * g2v, pc = s1 * g2v;
        float P[9];
        P[0] = pa;      P[1] = pb;      P[2] = pc;
        P[3] = c0 * pa; P[4] = c0 * pb; P[5] = c0 * pc;
        P[6] = s0 * pa; P[7] = s0 * pb; P[8] = s0 * pc;

        unsigned long long acc[9];
#pragma unroll
        for (int i = 0; i < 9; i++) acc[i] = 0ull;

#pragma unroll
        for (int m01 = 0; m01 < 9; m01++) {
            unsigned long long p2 = pk2(P[m01]);
            unsigned ra = tb + m01 * 240;   // row stride = 3 rows * 80B
            unsigned long long t0, t1, t2, t3, t4, t5, t6, t7, t8;
            asm volatile("ld.shared.v2.b64 {%0,%1}, [%2];"
                         : "=l"(t0), "=l"(t1) : "r"(ra));
            asm volatile("ld.shared.v2.b64 {%0,%1}, [%2];"
                         : "=l"(t2), "=l"(t3) : "r"(ra + 16));
            asm volatile("ld.shared.v2.b64 {%0,%1}, [%2];"
                         : "=l"(t4), "=l"(t5) : "r"(ra + 32));
            asm volatile("ld.shared.v2.b64 {%0,%1}, [%2];"
                         : "=l"(t6), "=l"(t7) : "r"(ra + 48));
            asm volatile("ld.shared.b64 %0, [%1];"
                         : "=l"(t8) : "r"(ra + 64));
            acc[0] = fma2(p2, t0, acc[0]);
            acc[1] = fma2(p2, t1, acc[1]);
            acc[2] = fma2(p2, t2, acc[2]);
            acc[3] = fma2(p2, t3, acc[3]);
            acc[4] = fma2(p2, t4, acc[4]);
            acc[5] = fma2(p2, t5, acc[5]);
            acc[6] = fma2(p2, t6, acc[6]);
            acc[7] = fma2(p2, t7, acc[7]);
            acc[8] = fma2(p2, t8, acc[8]);
        }

        // Q(h) dot: acc[i] = (S_{j0,mh=i}, S_{j1,mh=i})
        float sh0, ch0, sh1, ch1;
        __sincosf(h0, &sh0, &ch0);
        __sincosf(h1, &sh1, &ch1);
        unsigned long long a = acc[0];                       // Q[0] = 1
        a = fma2(pk2(ch1),       acc[1], a);
        a = fma2(pk2(sh1),       acc[2], a);
        a = fma2(pk2(ch0),       acc[3], a);
        a = fma2(pk2(ch0 * ch1), acc[4], a);
        a = fma2(pk2(ch0 * sh1), acc[5], a);
        a = fma2(pk2(sh0),       acc[6], a);
        a = fma2(pk2(sh0 * ch1), acc[7], a);
        a = fma2(pk2(sh0 * sh1), acc[8], a);

        float a0, a1;
        asm("mov.b64 {%0,%1}, %2;" : "=f"(a0), "=f"(a1) : "l"(a));
        // quad reduction (lanes of one b)
        a0 += __shfl_xor_sync(0xffffffffu, a0, 1, 4);
        a0 += __shfl_xor_sync(0xffffffffu, a0, 2, 4);
        a1 += __shfl_xor_sync(0xffffffffu, a1, 1, 4);
        a1 += __shfl_xor_sync(0xffffffffu, a1, 2, 4);
        h0 = a0;
        h1 = a1;

        xc0 = xn0; xc1 = xn1; xc2 = xn2;
    }

    // Readout (one lane per quad)
    if (ql == 0) {
        float To[9];
#pragma unroll
        for (int i = 0; i < 9; i++) To[i] = d_To[i];
        float sh0, ch0, sh1, ch1;
        __sincosf(h0, &sh0, &ch0);
        __sincosf(h1, &sh1, &ch1);
        float Q[9] = {1.f, ch1, sh1, ch0, ch0 * ch1, ch0 * sh1,
                      sh0, sh0 * ch1, sh0 * sh1};
        float r = 0.f;
#pragma unroll
        for (int m = 0; m < 9; m++) r += To[m] * Q[m];
        out[b] = r;
    }
}

// ---------------------------------------------------------------------------
extern "C" void kernel_launch(void* const* d_in, const int* in_sizes, int n_in,
                              void* d_out, int out_size) {
    const float* x_seq = nullptr;
    const float* w_rec = nullptr;
    const float* w_out = nullptr;
    for (int i = 0; i < n_in; i++) {
        if (in_sizes[i] == T_SZ * B_SZ * 3) x_seq = (const float*)d_in[i];
        else if (in_sizes[i] == 30)         w_rec = (const float*)d_in[i];
        else if (in_sizes[i] == 12)         w_out = (const float*)d_in[i];
    }
    float* out = (float*)d_out;

    precompute_kernel<<<1, 1024>>>(w_rec, w_out);
    main_kernel<<<(B_SZ * 4) / 256, 256>>>(x_seq, out);
}

// round 6
// speedup vs baseline: 2.4227x; 1.3698x over previous
#include <cuda_runtime.h>

#define B_SZ 8192
#define T_SZ 32

// Static device scratch
__device__ float d_Tp[27 * 20];                 // [mx][k], k = mh*2+j, pads 0
__device__ float d_To[9];                       // readout tensor
__device__ float4 d_S4[T_SZ * 5 * B_SZ];        // [t][q][b] float4 (21MB)

__device__ __forceinline__ float2 cmul(float2 a, float2 b) {
    return make_float2(a.x * b.x - a.y * b.y, a.x * b.y + a.y * b.x);
}
__device__ __forceinline__ unsigned long long fma2(unsigned long long a,
                                                   unsigned long long b,
                                                   unsigned long long c) {
    unsigned long long d;
    asm("fma.rn.f32x2 %0, %1, %2, %3;" : "=l"(d) : "l"(a), "l"(b), "l"(c));
    return d;
}
__device__ __forceinline__ unsigned long long pk2(float x) {
    unsigned long long r;
    asm("mov.b64 %0, {%1, %1};" : "=l"(r) : "f"(x));
    return r;
}
__device__ __forceinline__ void cpa16(void* smem, const void* gmem) {
    unsigned s = (unsigned)__cvta_generic_to_shared(smem);
    asm volatile("cp.async.cg.shared.global [%0], [%1], 16;"
                 :: "r"(s), "l"(gmem) : "memory");
}

// ---------------------------------------------------------------------------
// Precompute (1 block, 1024 threads). Conflict-free smem (real/imag planes).
// ---------------------------------------------------------------------------
__global__ void __launch_bounds__(1024) precompute_kernel(const float* __restrict__ wrec,
                                                          const float* __restrict__ wout) {
    __shared__ float2 G[10][4];
    __shared__ float UsR[32][33];
    __shared__ float UsI[32][33];
    __shared__ float Ms[2][32][33];
    const int tid = threadIdx.x;

    if (tid < 10) {
        float phi = wrec[tid * 3 + 0];
        float th  = wrec[tid * 3 + 1];
        float om  = wrec[tid * 3 + 2];
        float s, c, sa, ca, sb, cb;
        __sincosf(0.5f * th, &s, &c);
        __sincosf(0.5f * (phi + om), &sa, &ca);
        __sincosf(0.5f * (phi - om), &sb, &cb);
        G[tid][0] = make_float2( c * ca, -c * sa);
        G[tid][1] = make_float2(-s * cb, -s * sb);
        G[tid][2] = make_float2( s * cb, -s * sb);
        G[tid][3] = make_float2( c * ca,  c * sa);
    }
    {
        int row = tid >> 5, col = tid & 31;
        UsR[row][col] = (row == col) ? 1.f : 0.f;
        UsI[row][col] = 0.f;
    }
    __syncthreads();

#pragma unroll
    for (int l = 0; l < 2; l++) {
#pragma unroll
        for (int w = 0; w < 5; w++) {
            if (tid < 512) {
                int col = tid & 31, p = tid >> 5;
                int mask = 1 << (4 - w);
                int low = mask - 1;
                int i0 = ((p & ~low) << 1) | (p & low);
                int i1 = i0 | mask;
                float2 r00 = G[l * 5 + w][0], r01 = G[l * 5 + w][1];
                float2 r10 = G[l * 5 + w][2], r11 = G[l * 5 + w][3];
                float2 a0 = make_float2(UsR[i0][col], UsI[i0][col]);
                float2 a1 = make_float2(UsR[i1][col], UsI[i1][col]);
                float2 n0 = cmul(r00, a0), u01 = cmul(r01, a1);
                n0.x += u01.x; n0.y += u01.y;
                float2 n1 = cmul(r10, a0), u11 = cmul(r11, a1);
                n1.x += u11.x; n1.y += u11.y;
                UsR[i0][col] = n0.x; UsI[i0][col] = n0.y;
                UsR[i1][col] = n1.x; UsI[i1][col] = n1.y;
            }
            __syncthreads();
        }
        {
            int row = tid >> 5, col = tid & 31;
            int rr = l + 1;
            int j = row;
#pragma unroll
            for (int w = 4; w >= 0; w--) {
                int cm = 1 << (4 - w);
                int tm = 1 << (4 - ((w + rr) % 5));
                if (j & cm) j ^= tm;
            }
            float vr = UsR[j][col], vi = UsI[j][col];
            __syncthreads();
            UsR[row][col] = vr;
            UsI[row][col] = vi;
            __syncthreads();
        }
    }

    {
        int s = tid >> 5, t = tid & 31;
        float m0 = 0.f, m1 = 0.f;
#pragma unroll
        for (int k = 0; k < 32; k++) {
            float ar = UsR[k][s], ai = UsI[k][s];
            float br = UsR[k][t], bi = UsI[k][t];
            float re = ar * br + ai * bi;
            m0 += ((k >> 1) & 1) ? -re : re;
            m1 += (k & 1) ? -re : re;
        }
        Ms[0][s][t] = m0;
        Ms[1][s][t] = m1;
    }
    __syncthreads();

    if (tid < 486) {
        int j = tid / 243, m = tid % 243;
        int dg[5];
        int mm = m;
#pragma unroll
        for (int w = 4; w >= 0; w--) { dg[w] = mm % 3; mm /= 3; }
        int emask = 0, xmask = 0;
#pragma unroll
        for (int w = 0; w < 5; w++) {
            if (dg[w] == 1) emask |= 1 << (4 - w);
            if (dg[w] == 2) xmask |= 1 << (4 - w);
        }
        float sum = 0.f;
#pragma unroll
        for (int u = 0; u < 32; u++) {
            float sgn = (__popc(u & emask) & 1) ? -1.f : 1.f;
            sum += sgn * Ms[j][u][u ^ xmask];
        }
        d_Tp[(m / 9) * 20 + (m % 9) * 2 + j] = sum * (1.f / 32.f);
    }
    if (tid >= 640 && tid < 640 + 54) {
        int i = tid - 640;
        d_Tp[(i >> 1) * 20 + 18 + (i & 1)] = 0.f;
    }

    if (tid >= 512 && tid < 521) {
        int m = tid - 512;
        float2 V[4][4];
#pragma unroll
        for (int c2 = 0; c2 < 4; c2++)
#pragma unroll
            for (int r2 = 0; r2 < 4; r2++)
                V[c2][r2] = make_float2(c2 == r2 ? 1.f : 0.f, 0.f);
#pragma unroll
        for (int l = 0; l < 2; l++) {
#pragma unroll
            for (int w = 0; w < 2; w++) {
                float phi = wout[(l * 2 + w) * 3 + 0];
                float th  = wout[(l * 2 + w) * 3 + 1];
                float om  = wout[(l * 2 + w) * 3 + 2];
                float s, c, sa, ca, sb, cb;
                __sincosf(0.5f * th, &s, &c);
                __sincosf(0.5f * (phi + om), &sa, &ca);
                __sincosf(0.5f * (phi - om), &sb, &cb);
                float2 r00 = make_float2( c * ca, -c * sa);
                float2 r01 = make_float2(-s * cb, -s * sb);
                float2 r10 = make_float2( s * cb, -s * sb);
                float2 r11 = make_float2( c * ca,  c * sa);
                int mask = 1 << (1 - w);
#pragma unroll
                for (int col = 0; col < 4; col++) {
#pragma unroll
                    for (int i0 = 0; i0 < 4; i0++) {
                        if (i0 & mask) continue;
                        int i1 = i0 | mask;
                        float2 a0 = V[col][i0], a1 = V[col][i1];
                        float2 n0 = cmul(r00, a0), u01 = cmul(r01, a1);
                        n0.x += u01.x; n0.y += u01.y;
                        float2 n1 = cmul(r10, a0), u11 = cmul(r11, a1);
                        n1.x += u11.x; n1.y += u11.y;
                        V[col][i0] = n0;
                        V[col][i1] = n1;
                    }
                }
            }
#pragma unroll
            for (int w = 0; w < 2; w++) {
                int cm = 1 << (1 - w), tm = 1 << (1 - ((w + 1) & 1));
#pragma unroll
                for (int col = 0; col < 4; col++)
#pragma unroll
                    for (int row = 0; row < 4; row++)
                        if ((row & cm) && !(row & tm)) {
                            float2 a = V[col][row], b2 = V[col][row | tm];
                            V[col][row] = b2;
                            V[col][row | tm] = a;
                        }
            }
        }
        float Mo[4][4];
#pragma unroll
        for (int s = 0; s < 4; s++)
#pragma unroll
            for (int t = 0; t < 4; t++) {
                float acc = 0.f;
#pragma unroll
                for (int k = 0; k < 4; k++) {
                    float2 vs = V[s][k], vt = V[t][k];
                    float re = vs.x * vt.x + vs.y * vt.y;
                    acc += ((k >> 1) & 1) ? -re : re;
                }
                Mo[s][t] = acc;
            }
        int d0 = m / 3, d1 = m % 3;
        int emask = (d0 == 1 ? 2 : 0) | (d1 == 1 ? 1 : 0);
        int xmask = (d0 == 2 ? 2 : 0) | (d1 == 2 ? 1 : 0);
        float sum = 0.f;
#pragma unroll
        for (int u = 0; u < 4; u++) {
            float sgn = (__popc(u & emask) & 1) ? -1.f : 1.f;
            sum += sgn * Mo[u][u ^ xmask];
        }
        d_To[m] = sum * 0.25f;
    }
}

// ---------------------------------------------------------------------------
// Phase 1: S[t][q][b] = (P(x[t,b]) . T) packed as float4s.
// T reads are warp-uniform -> smem broadcast (conflict-free). FMA-bound.
// ---------------------------------------------------------------------------
__global__ void __launch_bounds__(256) phase1_kernel(const float* __restrict__ x_seq) {
    __shared__ __align__(16) float Ts[27 * 20];
    const int tid = threadIdx.x;
    for (int i = tid; i < 540; i += 256) Ts[i] = d_Tp[i];
    __syncthreads();

    int e = blockIdx.x * 256 + tid;
    int b = e & (B_SZ - 1);
    int t = e >> 13;
    const float* xp = x_seq + ((size_t)t * B_SZ + b) * 3;
    float x0 = xp[0], x1 = xp[1], x2 = xp[2];
    float s0, c0, s1, c1, s2, c2;
    __sincosf(x0, &s0, &c0);
    __sincosf(x1, &s1, &c1);
    __sincosf(x2, &s2, &c2);
    float g0[3] = {1.f, c0, s0};
    float g1[3] = {1.f, c1, s1};
    float g2[3] = {1.f, c2, s2};

    unsigned long long acc[10];
#pragma unroll
    for (int q = 0; q < 10; q++) acc[q] = 0ull;

    unsigned tbase = (unsigned)__cvta_generic_to_shared(Ts);
#pragma unroll
    for (int m0 = 0; m0 < 3; m0++) {
#pragma unroll
        for (int m1 = 0; m1 < 3; m1++) {
            float p01 = g0[m0] * g1[m1];
#pragma unroll
            for (int m2 = 0; m2 < 3; m2++) {
                float p = p01 * g2[m2];
                unsigned long long p2 = pk2(p);
                int mx = (m0 * 3 + m1) * 3 + m2;
                unsigned ra = tbase + mx * 80;
#pragma unroll
                for (int q = 0; q < 5; q++) {
                    unsigned long long t0, t1;
                    asm volatile("ld.shared.v2.b64 {%0,%1}, [%2];"
                                 : "=l"(t0), "=l"(t1) : "r"(ra + q * 16));
                    acc[2 * q]     = fma2(p2, t0, acc[2 * q]);
                    acc[2 * q + 1] = fma2(p2, t1, acc[2 * q + 1]);
                }
            }
        }
    }

#pragma unroll
    for (int q = 0; q < 5; q++) {
        float l0, h0v, l1, h1v;
        asm("mov.b64 {%0,%1}, %2;" : "=f"(l0), "=f"(h0v) : "l"(acc[2 * q]));
        asm("mov.b64 {%0,%1}, %2;" : "=f"(l1), "=f"(h1v) : "l"(acc[2 * q + 1]));
        d_S4[((size_t)t * 5 + q) * B_SZ + b] = make_float4(l0, h0v, l1, h1v);
    }
}

// ---------------------------------------------------------------------------
// Phase 2: recurrence with cp.async-staged S (7-deep pipeline -> full BW).
// Each thread cp.asyncs exactly the 16B chunks it reads; wait_group syncs.
// ---------------------------------------------------------------------------
__global__ void __launch_bounds__(64) phase2_kernel(float* __restrict__ out) {
    __shared__ __align__(16) float4 sbuf[8][5][64];   // 40KB
    const int tid = threadIdx.x;
    const int b = blockIdx.x * 64 + tid;

    // prologue: slots 0..6
#pragma unroll
    for (int t = 0; t < 7; t++) {
#pragma unroll
        for (int q = 0; q < 5; q++)
            cpa16(&sbuf[t][q][tid], &d_S4[((size_t)t * 5 + q) * B_SZ + b]);
        asm volatile("cp.async.commit_group;" ::: "memory");
    }

    float h0 = 0.f, h1 = 0.f;
#pragma unroll
    for (int t = 0; t < T_SZ; t++) {
        asm volatile("cp.async.wait_group 6;" ::: "memory");
        float4 v[5];
#pragma unroll
        for (int q = 0; q < 5; q++) v[q] = sbuf[t & 7][q][tid];

        if (t + 7 < T_SZ) {
#pragma unroll
            for (int q = 0; q < 5; q++)
                cpa16(&sbuf[(t + 7) & 7][q][tid],
                      &d_S4[((size_t)(t + 7) * 5 + q) * B_SZ + b]);
        }
        asm volatile("cp.async.commit_group;" ::: "memory");

        float Sc[20];
#pragma unroll
        for (int q = 0; q < 5; q++) {
            Sc[4 * q + 0] = v[q].x;
            Sc[4 * q + 1] = v[q].y;
            Sc[4 * q + 2] = v[q].z;
            Sc[4 * q + 3] = v[q].w;
        }
        float sh0, ch0, sh1, ch1;
        __sincosf(h0, &sh0, &ch0);
        __sincosf(h1, &sh1, &ch1);
        float Q[9];
        Q[0] = 1.f;        Q[1] = ch1;        Q[2] = sh1;
        Q[3] = ch0;        Q[4] = ch0 * ch1;  Q[5] = ch0 * sh1;
        Q[6] = sh0;        Q[7] = sh0 * ch1;  Q[8] = sh0 * sh1;
        float a0 = 0.f, a1 = 0.f;
#pragma unroll
        for (int mh = 0; mh < 9; mh++) {
            a0 += Sc[2 * mh] * Q[mh];
            a1 += Sc[2 * mh + 1] * Q[mh];
        }
        h0 = a0;
        h1 = a1;
    }

    // Readout
    float To[9];
#pragma unroll
    for (int i = 0; i < 9; i++) To[i] = d_To[i];
    float sh0, ch0, sh1, ch1;
    __sincosf(h0, &sh0, &ch0);
    __sincosf(h1, &sh1, &ch1);
    float Q[9] = {1.f, ch1, sh1, ch0, ch0 * ch1, ch0 * sh1,
                  sh0, sh0 * ch1, sh0 * sh1};
    float r = 0.f;
#pragma unroll
    for (int m = 0; m < 9; m++) r += To[m] * Q[m];
    out[b] = r;
}

// ---------------------------------------------------------------------------
extern "C" void kernel_launch(void* const* d_in, const int* in_sizes, int n_in,
                              void* d_out, int out_size) {
    const float* x_seq = nullptr;
    const float* w_rec = nullptr;
    const float* w_out = nullptr;
    for (int i = 0; i < n_in; i++) {
        if (in_sizes[i] == T_SZ * B_SZ * 3) x_seq = (const float*)d_in[i];
        else if (in_sizes[i] == 30)         w_rec = (const float*)d_in[i];
        else if (in_sizes[i] == 12)         w_out = (const float*)d_in[i];
    }
    float* out = (float*)d_out;

    precompute_kernel<<<1, 1024>>>(w_rec, w_out);
    phase1_kernel<<<(T_SZ * B_SZ) / 256, 256>>>(x_seq);
    phase2_kernel<<<B_SZ / 64, 64>>>(out);
}